// round 1
// baseline (speedup 1.0000x reference)
#include <cuda_runtime.h>

// Problem constants
#define SQ 512
#define BB 32
#define HH 1024
#define GG 4096           // 4*HH
#define LL 3
#define MM (SQ*BB)        // 16384 rows for input GEMM
#define NBLK 128          // persistent blocks for recurrence
#define CK 128            // K-chunk for h streaming

// ------------------------- scratch (device globals; no cudaMalloc allowed) ---
__device__ float g_seqA[(size_t)MM * HH];     // 64 MB
__device__ float g_seqB[(size_t)MM * HH];     // 64 MB
__device__ float g_G[(size_t)MM * GG];        // 256 MB gate preactivations
__device__ float g_hT[LL * BB * HH];          // encoder final h per layer
__device__ float g_cT[LL * BB * HH];          // encoder final c per layer

__device__ unsigned g_bar_cnt = 0;
__device__ volatile unsigned g_bar_gen = 0;

// ------------------------- grid barrier (all NBLK blocks co-resident) --------
__device__ __forceinline__ void grid_barrier(int nblk) {
    __syncthreads();
    if (threadIdx.x == 0) {
        unsigned g0 = g_bar_gen;
        __threadfence();
        unsigned ticket = atomicAdd(&g_bar_cnt, 1u);
        if (ticket == (unsigned)(nblk - 1)) {
            g_bar_cnt = 0;
            __threadfence();
            g_bar_gen = g0 + 1u;
        } else {
            while (g_bar_gen == g0) { }
        }
        __threadfence();
    }
    __syncthreads();
}

// ------------------------- embedding gather ---------------------------------
__global__ void gather_kernel(const int* __restrict__ x,
                              const float* __restrict__ emb,
                              float* __restrict__ out) {
    const int total = MM * (HH / 4);
    for (int i = blockIdx.x * blockDim.x + threadIdx.x; i < total;
         i += gridDim.x * blockDim.x) {
        int row = i >> 8;          // / (HH/4)
        int col = i & 255;
        int tok = __ldg(x + row);
        float4 v = __ldg(((const float4*)(emb + (size_t)tok * HH)) + col);
        ((float4*)out)[i] = v;
    }
}

// ------------------------- input GEMM: C[M,N] = A[M,K] @ W[N,K]^T + bias -----
// M=MM, N=GG, K=HH. Tiles: 128x128x16, 256 threads, 8x8 per thread.
__global__ __launch_bounds__(256) void igemm_kernel(
    const float* __restrict__ A, const float* __restrict__ W,
    const float* __restrict__ bias, float* __restrict__ C) {
    __shared__ float As[16][132];
    __shared__ float Bs[16][132];
    const int tid = threadIdx.x;
    const int bm = blockIdx.y * 128;
    const int bn = blockIdx.x * 128;
    const int tx = tid & 15;
    const int ty = tid >> 4;
    const int r0 = tid >> 2;            // 0..63
    const int kq0 = (tid & 3) << 2;     // 0,4,8,12

    float acc[8][8];
#pragma unroll
    for (int i = 0; i < 8; ++i)
#pragma unroll
        for (int j = 0; j < 8; ++j) acc[i][j] = 0.f;

    for (int k0 = 0; k0 < HH; k0 += 16) {
#pragma unroll
        for (int j = 0; j < 2; ++j) {
            int row = r0 + j * 64;
            float4 va = __ldg((const float4*)(A + (size_t)(bm + row) * HH + k0 + kq0));
            As[kq0 + 0][row] = va.x; As[kq0 + 1][row] = va.y;
            As[kq0 + 2][row] = va.z; As[kq0 + 3][row] = va.w;
            float4 vb = __ldg((const float4*)(W + (size_t)(bn + row) * HH + k0 + kq0));
            Bs[kq0 + 0][row] = vb.x; Bs[kq0 + 1][row] = vb.y;
            Bs[kq0 + 2][row] = vb.z; Bs[kq0 + 3][row] = vb.w;
        }
        __syncthreads();
#pragma unroll
        for (int k = 0; k < 16; ++k) {
            float ra[8], rb[8];
            *(float4*)(ra)     = *(const float4*)(&As[k][ty * 8]);
            *(float4*)(ra + 4) = *(const float4*)(&As[k][ty * 8 + 4]);
            *(float4*)(rb)     = *(const float4*)(&Bs[k][tx * 8]);
            *(float4*)(rb + 4) = *(const float4*)(&Bs[k][tx * 8 + 4]);
#pragma unroll
            for (int i = 0; i < 8; ++i)
#pragma unroll
                for (int j = 0; j < 8; ++j)
                    acc[i][j] = fmaf(ra[i], rb[j], acc[i][j]);
        }
        __syncthreads();
    }
#pragma unroll
    for (int i = 0; i < 8; ++i) {
        size_t m = (size_t)(bm + ty * 8 + i);
#pragma unroll
        for (int j = 0; j < 8; j += 4) {
            int n = bn + tx * 8 + j;
            float4 bv = __ldg((const float4*)(bias + n));
            float4 o;
            o.x = acc[i][j + 0] + bv.x;
            o.y = acc[i][j + 1] + bv.y;
            o.z = acc[i][j + 2] + bv.z;
            o.w = acc[i][j + 3] + bv.w;
            *(float4*)(C + m * GG + n) = o;
        }
    }
}

// ------------------------- persistent recurrence ----------------------------
// 128 blocks x 256 threads. Block owns 8 hidden units (32 Whh rows in SMEM,
// loaded once). Thread (w=tid/32, lane=tid%32) owns unit u0+w, batch lane:
// all four gates + the c state live in its registers for the whole sequence.
__global__ __launch_bounds__(256) void recur_kernel(
    const float* __restrict__ Gin,   // [SQ*BB, GG] = x@Wih^T + b
    const float* __restrict__ Whh,   // [GG, HH]
    const float* __restrict__ h0,    // [BB,HH] or null (zeros)
    const float* __restrict__ c0,    // [BB,HH] or null (zeros)
    float* __restrict__ out,         // [SQ,BB,HH]
    float* __restrict__ hT,          // [BB,HH] or null
    float* __restrict__ cT) {        // [BB,HH] or null
    extern __shared__ float sh[];
    float* Wsh = sh;                  // [32][HH]   128 KB
    float* hsh = sh + 32 * HH;        // [CK][33]   16.5 KB
    const int tid = threadIdx.x;
    const int u0 = blockIdx.x * 8;
    const int w = tid >> 5;
    const int lane = tid & 31;

    // Load this block's 32 Whh rows: local row lr = gate*8 + uu
    for (int i = tid; i < 32 * 256; i += 256) {
        int lr = i >> 8;
        int kq = i & 255;
        int gam = lr >> 3, uu = lr & 7;
        float4 v = __ldg((const float4*)(Whh + (size_t)(gam * HH + u0 + uu) * HH) + kq);
        ((float4*)(Wsh + (size_t)lr * HH))[kq] = v;
    }
    float c = (c0 != nullptr) ? c0[lane * HH + u0 + w] : 0.f;
    __syncthreads();

    const float* w0p = Wsh + (size_t)(0 * 8 + w) * HH;
    const float* w1p = Wsh + (size_t)(1 * 8 + w) * HH;
    const float* w2p = Wsh + (size_t)(2 * 8 + w) * HH;
    const float* w3p = Wsh + (size_t)(3 * 8 + w) * HH;

    float hlast = 0.f;
    for (int t = 0; t < SQ; ++t) {
        const float* hp = (t == 0) ? h0 : (out + (size_t)(t - 1) * BB * HH);
        float a0, a1, a2, a3;
        {
            const float* gb = Gin + ((size_t)t * BB + lane) * GG + u0 + w;
            a0 = __ldcg(gb);
            a1 = __ldcg(gb + HH);
            a2 = __ldcg(gb + 2 * HH);
            a3 = __ldcg(gb + 3 * HH);
        }
        if (hp != nullptr) {
            for (int k0 = 0; k0 < HH; k0 += CK) {
                __syncthreads();
                for (int i = tid; i < 32 * (CK / 4); i += 256) {
                    int b = i >> 5;
                    int kq = i & 31;
                    float4 v = __ldcg((const float4*)(hp + (size_t)b * HH + k0) + kq);
                    hsh[(kq * 4 + 0) * 33 + b] = v.x;
                    hsh[(kq * 4 + 1) * 33 + b] = v.y;
                    hsh[(kq * 4 + 2) * 33 + b] = v.z;
                    hsh[(kq * 4 + 3) * 33 + b] = v.w;
                }
                __syncthreads();
#pragma unroll 8
                for (int k = 0; k < CK; k += 4) {
                    float4 q0 = *(const float4*)(w0p + k0 + k);
                    float4 q1 = *(const float4*)(w1p + k0 + k);
                    float4 q2 = *(const float4*)(w2p + k0 + k);
                    float4 q3 = *(const float4*)(w3p + k0 + k);
                    float h0v = hsh[(k + 0) * 33 + lane];
                    float h1v = hsh[(k + 1) * 33 + lane];
                    float h2v = hsh[(k + 2) * 33 + lane];
                    float h3v = hsh[(k + 3) * 33 + lane];
                    a0 = fmaf(q0.x, h0v, a0); a1 = fmaf(q1.x, h0v, a1);
                    a2 = fmaf(q2.x, h0v, a2); a3 = fmaf(q3.x, h0v, a3);
                    a0 = fmaf(q0.y, h1v, a0); a1 = fmaf(q1.y, h1v, a1);
                    a2 = fmaf(q2.y, h1v, a2); a3 = fmaf(q3.y, h1v, a3);
                    a0 = fmaf(q0.z, h2v, a0); a1 = fmaf(q1.z, h2v, a1);
                    a2 = fmaf(q2.z, h2v, a2); a3 = fmaf(q3.z, h2v, a3);
                    a0 = fmaf(q0.w, h3v, a0); a1 = fmaf(q1.w, h3v, a1);
                    a2 = fmaf(q2.w, h3v, a2); a3 = fmaf(q3.w, h3v, a3);
                }
            }
        }
        float iv = 1.f / (1.f + expf(-a0));
        float fv = 1.f / (1.f + expf(-a1));
        float gv = tanhf(a2);
        float ov = 1.f / (1.f + expf(-a3));
        c = fv * c + iv * gv;
        float hv = ov * tanhf(c);
        __stcg(out + (size_t)t * BB * HH + (size_t)lane * HH + u0 + w, hv);
        hlast = hv;
        grid_barrier(NBLK);
    }
    if (hT != nullptr) hT[lane * HH + u0 + w] = hlast;
    if (cT != nullptr) cT[lane * HH + u0 + w] = c;
}

// ------------------------- launch ------------------------------------------
extern "C" void kernel_launch(void* const* d_in, const int* in_sizes, int n_in,
                              void* d_out, int out_size) {
    const int*   x       = (const int*)d_in[0];
    const float* emb_enc = (const float*)d_in[1];
    const float* enc_Wih = (const float*)d_in[2];
    const float* enc_Whh = (const float*)d_in[3];
    const float* enc_b   = (const float*)d_in[4];
    const float* emb_dec = (const float*)d_in[5];
    const float* dec_Wih = (const float*)d_in[6];
    const float* dec_Whh = (const float*)d_in[7];
    const float* dec_b   = (const float*)d_in[8];
    float* out = (float*)d_out;

    float *seqA, *seqB, *G, *hT, *cT;
    cudaGetSymbolAddress((void**)&seqA, g_seqA);
    cudaGetSymbolAddress((void**)&seqB, g_seqB);
    cudaGetSymbolAddress((void**)&G,    g_G);
    cudaGetSymbolAddress((void**)&hT,   g_hT);
    cudaGetSymbolAddress((void**)&cT,   g_cT);

    const int recur_smem = (32 * HH + CK * 33) * (int)sizeof(float); // 147968
    cudaFuncSetAttribute(recur_kernel,
                         cudaFuncAttributeMaxDynamicSharedMemorySize, recur_smem);

    dim3 ig_grid(GG / 128, MM / 128);  // (32, 128)

    // ---------------- encoder ----------------
    gather_kernel<<<2048, 256>>>(x, emb_enc, seqA);
    float* cur = seqA;
    float* nxt = seqB;
    for (int l = 0; l < LL; ++l) {
        igemm_kernel<<<ig_grid, 256>>>(cur, enc_Wih + (size_t)l * GG * HH,
                                       enc_b + (size_t)l * GG, G);
        recur_kernel<<<NBLK, 256, recur_smem>>>(
            G, enc_Whh + (size_t)l * GG * HH, nullptr, nullptr,
            nxt, hT + (size_t)l * BB * HH, cT + (size_t)l * BB * HH);
        float* tmp = cur; cur = nxt; nxt = tmp;
    }

    // ---------------- decoder ----------------
    // cur holds encoder top output (unused); reuse buffers.
    gather_kernel<<<2048, 256>>>(x, emb_dec, seqA);
    cur = seqA; nxt = seqB;
    for (int l = 0; l < LL; ++l) {
        igemm_kernel<<<ig_grid, 256>>>(cur, dec_Wih + (size_t)l * GG * HH,
                                       dec_b + (size_t)l * GG, G);
        float* target = (l == LL - 1) ? out : nxt;
        recur_kernel<<<NBLK, 256, recur_smem>>>(
            G, dec_Whh + (size_t)l * GG * HH,
            hT + (size_t)l * BB * HH, cT + (size_t)l * BB * HH,
            target, nullptr, nullptr);
        nxt = cur; cur = target;
    }
}

// round 2
// speedup vs baseline: 1.3140x; 1.3140x over previous
#include <cuda_runtime.h>

// Problem constants
#define SQ 512
#define BB 32
#define HH 1024
#define GG 4096           // 4*HH
#define LL 3
#define MM (SQ*BB)        // 16384 rows for input GEMM
#define NBLK 128          // persistent blocks for recurrence
#define CK 256            // K-chunk for h streaming
#define NCH (HH/CK)       // 4 chunks
#define RP (CK/2 + 2)     // 130 pair-slots per batch row (8B units), conflict-free

typedef unsigned long long ull;

// ---- packed f32x2 helpers (sm_100+) ----------------------------------------
__device__ __forceinline__ ull ffma2(ull a, ull b, ull c) {
    ull d;
    asm("fma.rn.f32x2 %0, %1, %2, %3;" : "=l"(d) : "l"(a), "l"(b), "l"(c));
    return d;
}
__device__ __forceinline__ ull dup2(float x) {
    ull d; unsigned u = __float_as_uint(x);
    asm("mov.b64 %0, {%1, %1};" : "=l"(d) : "r"(u));
    return d;
}
__device__ __forceinline__ ull packlo(float x) {   // (x, 0)
    ull d; unsigned u = __float_as_uint(x); unsigned z = 0;
    asm("mov.b64 %0, {%1, %2};" : "=l"(d) : "r"(u), "r"(z));
    return d;
}
__device__ __forceinline__ float sum2(ull v) {
    unsigned lo, hi;
    asm("mov.b64 {%0, %1}, %2;" : "=r"(lo), "=r"(hi) : "l"(v));
    return __uint_as_float(lo) + __uint_as_float(hi);
}

// ------------------------- scratch (device globals) --------------------------
__device__ float g_seqA[(size_t)MM * HH];     // 64 MB
__device__ float g_seqB[(size_t)MM * HH];     // 64 MB
__device__ float g_G[(size_t)MM * GG];        // 256 MB gate preactivations
__device__ float g_hT[LL * BB * HH];
__device__ float g_cT[LL * BB * HH];

__device__ unsigned g_bar_cnt = 0;
__device__ volatile unsigned g_bar_gen = 0;

// ------------------------- grid barrier --------------------------------------
__device__ __forceinline__ void grid_barrier(int nblk) {
    __syncthreads();
    if (threadIdx.x == 0) {
        unsigned g0 = g_bar_gen;
        __threadfence();
        unsigned ticket = atomicAdd(&g_bar_cnt, 1u);
        if (ticket == (unsigned)(nblk - 1)) {
            g_bar_cnt = 0;
            __threadfence();
            g_bar_gen = g0 + 1u;
        } else {
            while (g_bar_gen == g0) { }
        }
        __threadfence();
    }
    __syncthreads();
}

// ------------------------- embedding gather ----------------------------------
__global__ void gather_kernel(const int* __restrict__ x,
                              const float* __restrict__ emb,
                              float* __restrict__ out) {
    const int total = MM * (HH / 4);
    for (int i = blockIdx.x * blockDim.x + threadIdx.x; i < total;
         i += gridDim.x * blockDim.x) {
        int row = i >> 8;
        int col = i & 255;
        int tok = __ldg(x + row);
        float4 v = __ldg(((const float4*)(emb + (size_t)tok * HH)) + col);
        ((float4*)out)[i] = v;
    }
}

// ------------------------- input GEMM: C = A @ W^T + bias (f32x2) ------------
__global__ __launch_bounds__(256) void igemm_kernel(
    const float* __restrict__ A, const float* __restrict__ W,
    const float* __restrict__ bias, float* __restrict__ C) {
    __shared__ float As[16][132];
    __shared__ float Bs[16][132];
    const int tid = threadIdx.x;
    const int bm = blockIdx.y * 128;
    const int bn = blockIdx.x * 128;
    const int tx = tid & 15;
    const int ty = tid >> 4;
    const int r0 = tid >> 2;
    const int kq0 = (tid & 3) << 2;

    ull acc[8][4];
#pragma unroll
    for (int i = 0; i < 8; ++i)
#pragma unroll
        for (int j = 0; j < 4; ++j) acc[i][j] = 0ull;

    for (int k0 = 0; k0 < HH; k0 += 16) {
#pragma unroll
        for (int j = 0; j < 2; ++j) {
            int row = r0 + j * 64;
            float4 va = __ldg((const float4*)(A + (size_t)(bm + row) * HH + k0 + kq0));
            As[kq0 + 0][row] = va.x; As[kq0 + 1][row] = va.y;
            As[kq0 + 2][row] = va.z; As[kq0 + 3][row] = va.w;
            float4 vb = __ldg((const float4*)(W + (size_t)(bn + row) * HH + k0 + kq0));
            Bs[kq0 + 0][row] = vb.x; Bs[kq0 + 1][row] = vb.y;
            Bs[kq0 + 2][row] = vb.z; Bs[kq0 + 3][row] = vb.w;
        }
        __syncthreads();
#pragma unroll
        for (int k = 0; k < 16; ++k) {
            float ra[8];
            *(float4*)(ra)     = *(const float4*)(&As[k][ty * 8]);
            *(float4*)(ra + 4) = *(const float4*)(&As[k][ty * 8 + 4]);
            ulonglong2 rb0 = *(const ulonglong2*)(&Bs[k][tx * 8]);
            ulonglong2 rb1 = *(const ulonglong2*)(&Bs[k][tx * 8 + 4]);
#pragma unroll
            for (int i = 0; i < 8; ++i) {
                ull rad = dup2(ra[i]);
                acc[i][0] = ffma2(rad, rb0.x, acc[i][0]);
                acc[i][1] = ffma2(rad, rb0.y, acc[i][1]);
                acc[i][2] = ffma2(rad, rb1.x, acc[i][2]);
                acc[i][3] = ffma2(rad, rb1.y, acc[i][3]);
            }
        }
        __syncthreads();
    }
#pragma unroll
    for (int i = 0; i < 8; ++i) {
        size_t m = (size_t)(bm + ty * 8 + i);
#pragma unroll
        for (int jp = 0; jp < 4; jp += 2) {
            int n = bn + tx * 8 + jp * 2;
            float4 bv = __ldg((const float4*)(bias + n));
            unsigned l0, h0, l1, h1;
            asm("mov.b64 {%0, %1}, %2;" : "=r"(l0), "=r"(h0) : "l"(acc[i][jp]));
            asm("mov.b64 {%0, %1}, %2;" : "=r"(l1), "=r"(h1) : "l"(acc[i][jp + 1]));
            float4 o;
            o.x = __uint_as_float(l0) + bv.x;
            o.y = __uint_as_float(h0) + bv.y;
            o.z = __uint_as_float(l1) + bv.z;
            o.w = __uint_as_float(h1) + bv.w;
            *(float4*)(C + m * GG + n) = o;
        }
    }
}

// ------------------------- persistent recurrence -----------------------------
// 128 blocks x 256 threads. Block owns 8 hidden units (32 Whh rows in SMEM).
// Thread (w=tid/32, lane=tid%32): unit u0+w, batch lane. f32x2 gate FMAs,
// double-buffered h chunks (CK=256) so global h latency hides under compute.
__global__ __launch_bounds__(256, 1) void recur_kernel(
    const float* __restrict__ Gin,   // [SQ*BB, GG]
    const float* __restrict__ Whh,   // [GG, HH]
    const float* __restrict__ h0,    // [BB,HH] or null (zeros)
    const float* __restrict__ c0,    // [BB,HH] or null (zeros)
    float* __restrict__ out,         // [SQ,BB,HH]
    float* __restrict__ hT,
    float* __restrict__ cT) {
    extern __shared__ __align__(16) char shraw[];
    float* Wsh = (float*)shraw;                        // [32][HH] 128 KB
    ull*   hsh = (ull*)(shraw + 32 * HH * sizeof(float)); // [2][32][RP] 66.56 KB
    const int tid = threadIdx.x;
    const int u0 = blockIdx.x * 8;
    const int w = tid >> 5;
    const int lane = tid & 31;

    // Load this block's 32 Whh rows (gate-major local rows: lr = gate*8 + uu)
    for (int i = tid; i < 32 * 256; i += 256) {
        int lr = i >> 8;
        int kq = i & 255;
        int gam = lr >> 3, uu = lr & 7;
        float4 v = __ldg((const float4*)(Whh + (size_t)(gam * HH + u0 + uu) * HH) + kq);
        ((float4*)(Wsh + (size_t)lr * HH))[kq] = v;
    }
    float c = (c0 != nullptr) ? c0[lane * HH + u0 + w] : 0.f;
    __syncthreads();

    const float* w0p = Wsh + (size_t)(0 * 8 + w) * HH;
    const float* w1p = Wsh + (size_t)(1 * 8 + w) * HH;
    const float* w2p = Wsh + (size_t)(2 * 8 + w) * HH;
    const float* w3p = Wsh + (size_t)(3 * 8 + w) * HH;

    const int ldb = tid >> 6;        // base batch row for h loads (0..3)
    const int ldf = tid & 63;        // float4 column within chunk

    float hlast = 0.f;
    for (int t = 0; t < SQ; ++t) {
        const float* hp = (t == 0) ? h0 : (out + (size_t)(t - 1) * BB * HH);
        // gate preactivations from input GEMM
        ull acc0, acc1, acc2, acc3;
        {
            const float* gb = Gin + ((size_t)t * BB + lane) * GG + u0 + w;
            acc0 = packlo(__ldcg(gb));
            acc1 = packlo(__ldcg(gb + HH));
            acc2 = packlo(__ldcg(gb + 2 * HH));
            acc3 = packlo(__ldcg(gb + 3 * HH));
        }
        if (hp != nullptr) {
            float4 r[8];
            // prefetch chunk 0
#pragma unroll
            for (int j = 0; j < 8; ++j) {
                int b = ldb + j * 4;
                r[j] = __ldcg((const float4*)(hp + (size_t)b * HH) + ldf);
            }
            for (int cI = 0; cI < NCH; ++cI) {
                const int p = cI & 1;
                // store prefetched chunk into smem buffer p (pairs layout)
                ull* hbuf = hsh + (size_t)p * 32 * RP;
#pragma unroll
                for (int j = 0; j < 8; ++j) {
                    int b = ldb + j * 4;
                    *(float4*)(hbuf + (size_t)b * RP + 2 * ldf) = r[j];
                }
                __syncthreads();
                // prefetch next chunk
                if (cI + 1 < NCH) {
                    const float* hpc = hp + (cI + 1) * CK;
#pragma unroll
                    for (int j = 0; j < 8; ++j) {
                        int b = ldb + j * 4;
                        r[j] = __ldcg((const float4*)(hpc + (size_t)b * HH) + ldf);
                    }
                }
                // compute over chunk cI
                const int k0 = cI * CK;
                const ull* hb = hbuf + (size_t)lane * RP;
                const ulonglong2* w0d = (const ulonglong2*)(w0p + k0);
                const ulonglong2* w1d = (const ulonglong2*)(w1p + k0);
                const ulonglong2* w2d = (const ulonglong2*)(w2p + k0);
                const ulonglong2* w3d = (const ulonglong2*)(w3p + k0);
#pragma unroll 8
                for (int q = 0; q < CK / 4; ++q) {
                    ulonglong2 W0 = w0d[q];
                    ulonglong2 W1 = w1d[q];
                    ulonglong2 W2 = w2d[q];
                    ulonglong2 W3 = w3d[q];
                    ulonglong2 Hp = *(const ulonglong2*)(hb + 2 * q);
                    acc0 = ffma2(W0.x, Hp.x, acc0);
                    acc1 = ffma2(W1.x, Hp.x, acc1);
                    acc2 = ffma2(W2.x, Hp.x, acc2);
                    acc3 = ffma2(W3.x, Hp.x, acc3);
                    acc0 = ffma2(W0.y, Hp.y, acc0);
                    acc1 = ffma2(W1.y, Hp.y, acc1);
                    acc2 = ffma2(W2.y, Hp.y, acc2);
                    acc3 = ffma2(W3.y, Hp.y, acc3);
                }
                __syncthreads();
            }
        }
        float a0 = sum2(acc0);
        float a1 = sum2(acc1);
        float a2 = sum2(acc2);
        float a3 = sum2(acc3);
        float iv = 1.f / (1.f + expf(-a0));
        float fv = 1.f / (1.f + expf(-a1));
        float gv = tanhf(a2);
        float ov = 1.f / (1.f + expf(-a3));
        c = fv * c + iv * gv;
        float hv = ov * tanhf(c);
        __stcg(out + (size_t)t * BB * HH + (size_t)lane * HH + u0 + w, hv);
        hlast = hv;
        if (t != SQ - 1) grid_barrier(NBLK);
    }
    if (hT != nullptr) hT[lane * HH + u0 + w] = hlast;
    if (cT != nullptr) cT[lane * HH + u0 + w] = c;
}

// ------------------------- launch --------------------------------------------
extern "C" void kernel_launch(void* const* d_in, const int* in_sizes, int n_in,
                              void* d_out, int out_size) {
    const int*   x       = (const int*)d_in[0];
    const float* emb_enc = (const float*)d_in[1];
    const float* enc_Wih = (const float*)d_in[2];
    const float* enc_Whh = (const float*)d_in[3];
    const float* enc_b   = (const float*)d_in[4];
    const float* emb_dec = (const float*)d_in[5];
    const float* dec_Wih = (const float*)d_in[6];
    const float* dec_Whh = (const float*)d_in[7];
    const float* dec_b   = (const float*)d_in[8];
    float* out = (float*)d_out;

    float *seqA, *seqB, *G, *hT, *cT;
    cudaGetSymbolAddress((void**)&seqA, g_seqA);
    cudaGetSymbolAddress((void**)&seqB, g_seqB);
    cudaGetSymbolAddress((void**)&G,    g_G);
    cudaGetSymbolAddress((void**)&hT,   g_hT);
    cudaGetSymbolAddress((void**)&cT,   g_cT);

    const int recur_smem = 32 * HH * (int)sizeof(float)
                         + 2 * 32 * RP * (int)sizeof(ull);   // 197632 B
    cudaFuncSetAttribute(recur_kernel,
                         cudaFuncAttributeMaxDynamicSharedMemorySize, recur_smem);

    dim3 ig_grid(GG / 128, MM / 128);  // (32, 128)

    // ---------------- encoder ----------------
    gather_kernel<<<2048, 256>>>(x, emb_enc, seqA);
    float* cur = seqA;
    float* nxt = seqB;
    for (int l = 0; l < LL; ++l) {
        igemm_kernel<<<ig_grid, 256>>>(cur, enc_Wih + (size_t)l * GG * HH,
                                       enc_b + (size_t)l * GG, G);
        recur_kernel<<<NBLK, 256, recur_smem>>>(
            G, enc_Whh + (size_t)l * GG * HH, nullptr, nullptr,
            nxt, hT + (size_t)l * BB * HH, cT + (size_t)l * BB * HH);
        float* tmp = cur; cur = nxt; nxt = tmp;
    }

    // ---------------- decoder ----------------
    gather_kernel<<<2048, 256>>>(x, emb_dec, seqA);
    cur = seqA; nxt = seqB;
    for (int l = 0; l < LL; ++l) {
        igemm_kernel<<<ig_grid, 256>>>(cur, dec_Wih + (size_t)l * GG * HH,
                                       dec_b + (size_t)l * GG, G);
        float* target = (l == LL - 1) ? out : nxt;
        recur_kernel<<<NBLK, 256, recur_smem>>>(
            G, dec_Whh + (size_t)l * GG * HH,
            hT + (size_t)l * BB * HH, cT + (size_t)l * BB * HH,
            target, nullptr, nullptr);
        nxt = cur; cur = target;
    }
}